// round 5
// baseline (speedup 1.0000x reference)
#include <cuda_runtime.h>

#define BATCH 16
#define CIN   256
#define COUT  256
#define HGT   64
#define WID   64
#define SDIM  512
#define EPSV  1e-8f

#define CICHUNK 8
#define NCHUNK  (CIN / CICHUNK)         // 32
#define COTILE  128
#define SW_CISTRIDE (9 * COTILE + 8)    // 1160 floats (even -> 8B aligned pairs)
#define SX_ROWS 4
#define SX_COLS 68                      // 66 used (cols -1..64), pad to 68

__device__ float g_style[BATCH * CIN];
__device__ float g_denom[BATCH * COUT];

// ---------------------------------------------------------------------------
// Kernel 1: style[b,ci] = y[b,:] @ style_w[ci,:] + style_b[ci]
// One warp per (b,ci). 512 blocks x 8 warps = 4096 warps.
// ---------------------------------------------------------------------------
__global__ void style_kernel(const float* __restrict__ y,
                             const float* __restrict__ sw,
                             const float* __restrict__ sb) {
    int widx = blockIdx.x * 8 + (threadIdx.x >> 5);   // 0..4095
    int lane = threadIdx.x & 31;
    int b  = widx >> 8;
    int ci = widx & 255;
    const float* yr = y + b * SDIM;
    const float* wr = sw + (size_t)ci * SDIM;
    float acc = 0.f;
#pragma unroll
    for (int s = lane; s < SDIM; s += 32) acc = fmaf(yr[s], wr[s], acc);
#pragma unroll
    for (int off = 16; off > 0; off >>= 1)
        acc += __shfl_xor_sync(0xffffffffu, acc, off);
    if (lane == 0) g_style[b * CIN + ci] = acc + sb[ci];
}

// ---------------------------------------------------------------------------
// Kernel 2: denom[b,co] = rsqrt( sum_ci style[b,ci]^2 * sum_k w[co,ci,k]^2 + eps )
// Block per co. Phase 1: v[ci] = sum_k w^2 (one sync). Phase 2: warp per 2 b.
// ---------------------------------------------------------------------------
__global__ void denom_kernel(const float* __restrict__ w) {
    int co = blockIdx.x;
    int ci = threadIdx.x;
    __shared__ float v[CIN];
    const float* wp = w + (size_t)co * (CIN * 9) + ci * 9;
    float s = 0.f;
#pragma unroll
    for (int k = 0; k < 9; k++) s = fmaf(wp[k], wp[k], s);
    v[ci] = s;
    __syncthreads();

    int warp = threadIdx.x >> 5;
    int lane = threadIdx.x & 31;
#pragma unroll
    for (int bb = 0; bb < 2; bb++) {
        int b = warp * 2 + bb;
        float acc = 0.f;
#pragma unroll
        for (int c = lane; c < CIN; c += 32) {
            float st = g_style[b * CIN + c];
            acc = fmaf(st * st, v[c], acc);
        }
#pragma unroll
        for (int off = 16; off > 0; off >>= 1)
            acc += __shfl_xor_sync(0xffffffffu, acc, off);
        if (lane == 0) g_denom[b * COUT + co] = rsqrtf(acc + EPSV);
    }
}

// ---------------------------------------------------------------------------
// Kernel 3: shared-weight conv, style folded into x, demod folded into output.
// Block: 128 cout x (2 rows x 64 cols) of one b. 256 threads: 8co x 8px each.
// Accumulators paired over oc (FFMA2); w pairs come straight from LDS.64.
// ---------------------------------------------------------------------------
__global__ __launch_bounds__(256, 2)
void conv_kernel(const float* __restrict__ x,
                 const float* __restrict__ w,
                 const float* __restrict__ bias,
                 float* __restrict__ out) {
    __shared__ __align__(16) float sW[CICHUNK * SW_CISTRIDE];
    __shared__ __align__(16) float sX[CICHUNK * SX_ROWS * SX_COLS];
    __shared__ float sStyle[CIN];

    const int b   = blockIdx.z;
    const int co0 = blockIdx.y * COTILE;
    const int r0  = blockIdx.x * 2;
    const int tid = threadIdx.x;

    for (int i = tid; i < CIN; i += 256) sStyle[i] = g_style[b * CIN + i];

    const int cog     = tid >> 4;          // 0..15
    const int pxg     = tid & 15;          // 0..15
    const int orow    = pxg >> 3;          // 0..1
    const int colbase = (pxg & 7) * 8;     // 0..56
    const int cobase  = cog * 8;           // 0..120

    // acc2[p][q]: p = pixel 0..7, q = oc-pair 0..3; .lo = oc 2q, .hi = oc 2q+1
    unsigned long long acc2[8][4];
#pragma unroll
    for (int p = 0; p < 8; p++)
#pragma unroll
        for (int q = 0; q < 4; q++) acc2[p][q] = 0ull;

    for (int chunk = 0; chunk < NCHUNK; chunk++) {
        const int ci0 = chunk * CICHUNK;
        __syncthreads();  // smem reuse (also orders sStyle fill on first iter)

        // --- load W chunk: [ci][tap][co] ---
#pragma unroll
        for (int it = 0; it < 4; it++) {
            int idx = tid + it * 256;      // 0..1023 = 128co x 8ci
            int co  = idx >> 3;
            int ci  = idx & 7;
            const float* gp = w + (size_t)(co0 + co) * (CIN * 9) + (ci0 + ci) * 9;
            float* sp = sW + ci * SW_CISTRIDE + co;
#pragma unroll
            for (int k = 0; k < 9; k++) sp[k * COTILE] = gp[k];
        }

        // --- load X halo tile, style-scaled, zero-padded ---
        for (int idx = tid; idx < CICHUNK * SX_ROWS * SX_COLS; idx += 256) {
            int ci  = idx / (SX_ROWS * SX_COLS);
            int rem = idx - ci * (SX_ROWS * SX_COLS);
            int rr  = rem / SX_COLS;
            int cc  = rem - rr * SX_COLS;
            int grow = r0 - 1 + rr;
            int gcol = cc - 1;
            float v = 0.f;
            if (grow >= 0 && grow < HGT && gcol >= 0 && gcol < WID && cc < 66) {
                v = x[(((size_t)(b * CIN + ci0 + ci)) * HGT + grow) * WID + gcol]
                    * sStyle[ci0 + ci];
            }
            sX[idx] = v;
        }
        __syncthreads();

        // --- compute: 8 ci x 3 ky x 3 kx x 8 px x 4 oc-pairs ---
#pragma unroll
        for (int ci = 0; ci < CICHUNK; ci++) {
            const float* xrow = sX + ci * (SX_ROWS * SX_COLS) + orow * SX_COLS + colbase;
            const float* wrow = sW + ci * SW_CISTRIDE + cobase;
#pragma unroll
            for (int ky = 0; ky < 3; ky++) {
                // vectorized x loads: 16B-aligned (all index terms mult of 4)
                float xv[10];
                const float* xr = xrow + ky * SX_COLS;
                {
                    float4 a = *(const float4*)(xr);
                    float4 c = *(const float4*)(xr + 4);
                    float2 e = *(const float2*)(xr + 8);
                    xv[0]=a.x; xv[1]=a.y; xv[2]=a.z; xv[3]=a.w;
                    xv[4]=c.x; xv[5]=c.y; xv[6]=c.z; xv[7]=c.w;
                    xv[8]=e.x; xv[9]=e.y;
                }
#pragma unroll
                for (int kx = 0; kx < 3; kx++) {
                    // w pairs: direct 64-bit LDS, no packing movs
                    const float* wp = wrow + (ky * 3 + kx) * COTILE;
                    unsigned long long wq[4];
#pragma unroll
                    for (int q = 0; q < 4; q++)
                        wq[q] = *(const unsigned long long*)(wp + 2 * q);
#pragma unroll
                    for (int p = 0; p < 8; p++) {
                        unsigned long long xb;
                        asm("mov.b64 %0, {%1, %1};" : "=l"(xb) : "f"(xv[kx + p]));
#pragma unroll
                        for (int q = 0; q < 4; q++) {
                            asm("fma.rn.f32x2 %0, %1, %2, %0;"
                                : "+l"(acc2[p][q]) : "l"(wq[q]), "l"(xb));
                        }
                    }
                }
            }
        }
    }

    // --- epilogue: demod scale + bias, vectorized stores ---
    const int gr = r0 + orow;
#pragma unroll
    for (int q = 0; q < 4; q++) {
        int oc0 = co0 + cobase + 2 * q;
        float d0 = g_denom[b * COUT + oc0];
        float d1 = g_denom[b * COUT + oc0 + 1];
        float b0 = bias[oc0];
        float b1 = bias[oc0 + 1];
        float r0v[8], r1v[8];
#pragma unroll
        for (int p = 0; p < 8; p++) {
            float lo, hi;
            asm("mov.b64 {%0, %1}, %2;" : "=f"(lo), "=f"(hi) : "l"(acc2[p][q]));
            r0v[p] = fmaf(lo, d0, b0);
            r1v[p] = fmaf(hi, d1, b1);
        }
        float4* op0 = (float4*)(out + (((size_t)(b * COUT + oc0)) * HGT + gr) * WID + colbase);
        float4* op1 = (float4*)(out + (((size_t)(b * COUT + oc0 + 1)) * HGT + gr) * WID + colbase);
        op0[0] = make_float4(r0v[0], r0v[1], r0v[2], r0v[3]);
        op0[1] = make_float4(r0v[4], r0v[5], r0v[6], r0v[7]);
        op1[0] = make_float4(r1v[0], r1v[1], r1v[2], r1v[3]);
        op1[1] = make_float4(r1v[4], r1v[5], r1v[6], r1v[7]);
    }
}

// ---------------------------------------------------------------------------
extern "C" void kernel_launch(void* const* d_in, const int* in_sizes, int n_in,
                              void* d_out, int out_size) {
    const float* x   = (const float*)d_in[0];  // [16,256,64,64]
    const float* y   = (const float*)d_in[1];  // [16,512]
    const float* w   = (const float*)d_in[2];  // [256,256,3,3]
    const float* bs  = (const float*)d_in[3];  // [256]
    const float* swt = (const float*)d_in[4];  // [256,512]
    const float* sbv = (const float*)d_in[5];  // [256]
    float* out = (float*)d_out;

    style_kernel<<<BATCH * CIN / 8, 256>>>(y, swt, sbv);
    denom_kernel<<<COUT, 256>>>(w);

    dim3 grid(HGT / 2, COUT / COTILE, BATCH);  // (32, 2, 16)
    conv_kernel<<<grid, 256>>>(x, w, bs, out);
}

// round 6
// speedup vs baseline: 1.0003x; 1.0003x over previous
#include <cuda_runtime.h>

#define BATCH 16
#define CIN   256
#define COUT  256
#define HGT   64
#define WID   64
#define SDIM  512
#define EPSV  1e-8f

#define CICHUNK 8
#define NCHUNK  (CIN / CICHUNK)         // 32
#define COTILE  128
#define SW_CISTRIDE (9 * COTILE + 8)    // 1160 floats (even -> 8B aligned pairs)
#define SX_ROWS 4
#define SX_COLS 68                      // 66 used (cols -1..64), pad to 68

__device__ float g_style[BATCH * CIN];
__device__ float g_denom[BATCH * COUT];

// ---------------------------------------------------------------------------
// Kernel 1: style[b,ci] = y[b,:] @ style_w[ci,:] + style_b[ci]
// One warp per (b,ci). 512 blocks x 8 warps = 4096 warps.
// ---------------------------------------------------------------------------
__global__ void style_kernel(const float* __restrict__ y,
                             const float* __restrict__ sw,
                             const float* __restrict__ sb) {
    int widx = blockIdx.x * 8 + (threadIdx.x >> 5);   // 0..4095
    int lane = threadIdx.x & 31;
    int b  = widx >> 8;
    int ci = widx & 255;
    const float* yr = y + b * SDIM;
    const float* wr = sw + (size_t)ci * SDIM;
    float acc = 0.f;
#pragma unroll
    for (int s = lane; s < SDIM; s += 32) acc = fmaf(yr[s], wr[s], acc);
#pragma unroll
    for (int off = 16; off > 0; off >>= 1)
        acc += __shfl_xor_sync(0xffffffffu, acc, off);
    if (lane == 0) g_style[b * CIN + ci] = acc + sb[ci];
}

// ---------------------------------------------------------------------------
// Kernel 2: denom[b,co] = rsqrt( sum_ci style[b,ci]^2 * sum_k w[co,ci,k]^2 + eps )
// Block per co. Phase 1: v[ci] = sum_k w^2 (one sync). Phase 2: warp per 2 b.
// ---------------------------------------------------------------------------
__global__ void denom_kernel(const float* __restrict__ w) {
    int co = blockIdx.x;
    int ci = threadIdx.x;
    __shared__ float v[CIN];
    const float* wp = w + (size_t)co * (CIN * 9) + ci * 9;
    float s = 0.f;
#pragma unroll
    for (int k = 0; k < 9; k++) s = fmaf(wp[k], wp[k], s);
    v[ci] = s;
    __syncthreads();

    int warp = threadIdx.x >> 5;
    int lane = threadIdx.x & 31;
#pragma unroll
    for (int bb = 0; bb < 2; bb++) {
        int b = warp * 2 + bb;
        float acc = 0.f;
#pragma unroll
        for (int c = lane; c < CIN; c += 32) {
            float st = g_style[b * CIN + c];
            acc = fmaf(st * st, v[c], acc);
        }
#pragma unroll
        for (int off = 16; off > 0; off >>= 1)
            acc += __shfl_xor_sync(0xffffffffu, acc, off);
        if (lane == 0) g_denom[b * COUT + co] = rsqrtf(acc + EPSV);
    }
}

// ---------------------------------------------------------------------------
// Kernel 3: shared-weight conv, style folded into x, demod folded into output.
// Block: 128 cout x (2 rows x 64 cols) of one b. 256 threads: 8co x 8px each.
// Accumulators paired over oc (FFMA2); w pairs come straight from LDS.64.
// ---------------------------------------------------------------------------
__global__ __launch_bounds__(256, 2)
void conv_kernel(const float* __restrict__ x,
                 const float* __restrict__ w,
                 const float* __restrict__ bias,
                 float* __restrict__ out) {
    __shared__ __align__(16) float sW[CICHUNK * SW_CISTRIDE];
    __shared__ __align__(16) float sX[CICHUNK * SX_ROWS * SX_COLS];
    __shared__ float sStyle[CIN];

    const int b   = blockIdx.z;
    const int co0 = blockIdx.y * COTILE;
    const int r0  = blockIdx.x * 2;
    const int tid = threadIdx.x;

    for (int i = tid; i < CIN; i += 256) sStyle[i] = g_style[b * CIN + i];

    const int cog     = tid >> 4;          // 0..15
    const int pxg     = tid & 15;          // 0..15
    const int orow    = pxg >> 3;          // 0..1
    const int colbase = (pxg & 7) * 8;     // 0..56
    const int cobase  = cog * 8;           // 0..120

    // acc2[p][q]: p = pixel 0..7, q = oc-pair 0..3; .lo = oc 2q, .hi = oc 2q+1
    unsigned long long acc2[8][4];
#pragma unroll
    for (int p = 0; p < 8; p++)
#pragma unroll
        for (int q = 0; q < 4; q++) acc2[p][q] = 0ull;

    for (int chunk = 0; chunk < NCHUNK; chunk++) {
        const int ci0 = chunk * CICHUNK;
        __syncthreads();  // smem reuse (also orders sStyle fill on first iter)

        // --- load W chunk: [ci][tap][co] ---
#pragma unroll
        for (int it = 0; it < 4; it++) {
            int idx = tid + it * 256;      // 0..1023 = 128co x 8ci
            int co  = idx >> 3;
            int ci  = idx & 7;
            const float* gp = w + (size_t)(co0 + co) * (CIN * 9) + (ci0 + ci) * 9;
            float* sp = sW + ci * SW_CISTRIDE + co;
#pragma unroll
            for (int k = 0; k < 9; k++) sp[k * COTILE] = gp[k];
        }

        // --- load X halo tile, style-scaled, zero-padded ---
        for (int idx = tid; idx < CICHUNK * SX_ROWS * SX_COLS; idx += 256) {
            int ci  = idx / (SX_ROWS * SX_COLS);
            int rem = idx - ci * (SX_ROWS * SX_COLS);
            int rr  = rem / SX_COLS;
            int cc  = rem - rr * SX_COLS;
            int grow = r0 - 1 + rr;
            int gcol = cc - 1;
            float v = 0.f;
            if (grow >= 0 && grow < HGT && gcol >= 0 && gcol < WID && cc < 66) {
                v = x[(((size_t)(b * CIN + ci0 + ci)) * HGT + grow) * WID + gcol]
                    * sStyle[ci0 + ci];
            }
            sX[idx] = v;
        }
        __syncthreads();

        // --- compute: 8 ci x 3 ky x 3 kx x 8 px x 4 oc-pairs ---
#pragma unroll
        for (int ci = 0; ci < CICHUNK; ci++) {
            const float* xrow = sX + ci * (SX_ROWS * SX_COLS) + orow * SX_COLS + colbase;
            const float* wrow = sW + ci * SW_CISTRIDE + cobase;
#pragma unroll
            for (int ky = 0; ky < 3; ky++) {
                // vectorized x loads: 16B-aligned (all index terms mult of 4)
                float xv[10];
                const float* xr = xrow + ky * SX_COLS;
                {
                    float4 a = *(const float4*)(xr);
                    float4 c = *(const float4*)(xr + 4);
                    float2 e = *(const float2*)(xr + 8);
                    xv[0]=a.x; xv[1]=a.y; xv[2]=a.z; xv[3]=a.w;
                    xv[4]=c.x; xv[5]=c.y; xv[6]=c.z; xv[7]=c.w;
                    xv[8]=e.x; xv[9]=e.y;
                }
#pragma unroll
                for (int kx = 0; kx < 3; kx++) {
                    // w pairs: direct 64-bit LDS, no packing movs
                    const float* wp = wrow + (ky * 3 + kx) * COTILE;
                    unsigned long long wq[4];
#pragma unroll
                    for (int q = 0; q < 4; q++)
                        wq[q] = *(const unsigned long long*)(wp + 2 * q);
#pragma unroll
                    for (int p = 0; p < 8; p++) {
                        unsigned long long xb;
                        asm("mov.b64 %0, {%1, %1};" : "=l"(xb) : "f"(xv[kx + p]));
#pragma unroll
                        for (int q = 0; q < 4; q++) {
                            asm("fma.rn.f32x2 %0, %1, %2, %0;"
                                : "+l"(acc2[p][q]) : "l"(wq[q]), "l"(xb));
                        }
                    }
                }
            }
        }
    }

    // --- epilogue: demod scale + bias, vectorized stores ---
    const int gr = r0 + orow;
#pragma unroll
    for (int q = 0; q < 4; q++) {
        int oc0 = co0 + cobase + 2 * q;
        float d0 = g_denom[b * COUT + oc0];
        float d1 = g_denom[b * COUT + oc0 + 1];
        float b0 = bias[oc0];
        float b1 = bias[oc0 + 1];
        float r0v[8], r1v[8];
#pragma unroll
        for (int p = 0; p < 8; p++) {
            float lo, hi;
            asm("mov.b64 {%0, %1}, %2;" : "=f"(lo), "=f"(hi) : "l"(acc2[p][q]));
            r0v[p] = fmaf(lo, d0, b0);
            r1v[p] = fmaf(hi, d1, b1);
        }
        float4* op0 = (float4*)(out + (((size_t)(b * COUT + oc0)) * HGT + gr) * WID + colbase);
        float4* op1 = (float4*)(out + (((size_t)(b * COUT + oc0 + 1)) * HGT + gr) * WID + colbase);
        op0[0] = make_float4(r0v[0], r0v[1], r0v[2], r0v[3]);
        op0[1] = make_float4(r0v[4], r0v[5], r0v[6], r0v[7]);
        op1[0] = make_float4(r1v[0], r1v[1], r1v[2], r1v[3]);
        op1[1] = make_float4(r1v[4], r1v[5], r1v[6], r1v[7]);
    }
}

// ---------------------------------------------------------------------------
extern "C" void kernel_launch(void* const* d_in, const int* in_sizes, int n_in,
                              void* d_out, int out_size) {
    const float* x   = (const float*)d_in[0];  // [16,256,64,64]
    const float* y   = (const float*)d_in[1];  // [16,512]
    const float* w   = (const float*)d_in[2];  // [256,256,3,3]
    const float* bs  = (const float*)d_in[3];  // [256]
    const float* swt = (const float*)d_in[4];  // [256,512]
    const float* sbv = (const float*)d_in[5];  // [256]
    float* out = (float*)d_out;

    style_kernel<<<BATCH * CIN / 8, 256>>>(y, swt, sbv);
    denom_kernel<<<COUT, 256>>>(w);

    dim3 grid(HGT / 2, COUT / COTILE, BATCH);  // (32, 2, 16)
    conv_kernel<<<grid, 256>>>(x, w, bs, out);
}

// round 7
// speedup vs baseline: 1.0014x; 1.0011x over previous
#include <cuda_runtime.h>

#define BATCH 16
#define CIN   256
#define COUT  256
#define HGT   64
#define WID   64
#define SDIM  512
#define EPSV  1e-8f

#define CICHUNK 8
#define NCHUNK  (CIN / CICHUNK)         // 32
#define COTILE  128
#define SW_CISTRIDE (9 * COTILE + 8)    // 1160 floats (even -> 8B aligned pairs)
#define SX_ROWS 4
#define SX_COLS 68                      // 66 used (cols -1..64), pad to 68

__device__ float g_style[BATCH * CIN];
__device__ float g_denom[BATCH * COUT];

// ---------------------------------------------------------------------------
// Kernel 1: style[b,ci] = y[b,:] @ style_w[ci,:] + style_b[ci]
// One warp per (b,ci). 512 blocks x 8 warps = 4096 warps.
// ---------------------------------------------------------------------------
__global__ void style_kernel(const float* __restrict__ y,
                             const float* __restrict__ sw,
                             const float* __restrict__ sb) {
    int widx = blockIdx.x * 8 + (threadIdx.x >> 5);   // 0..4095
    int lane = threadIdx.x & 31;
    int b  = widx >> 8;
    int ci = widx & 255;
    const float* yr = y + b * SDIM;
    const float* wr = sw + (size_t)ci * SDIM;
    float acc = 0.f;
#pragma unroll
    for (int s = lane; s < SDIM; s += 32) acc = fmaf(yr[s], wr[s], acc);
#pragma unroll
    for (int off = 16; off > 0; off >>= 1)
        acc += __shfl_xor_sync(0xffffffffu, acc, off);
    if (lane == 0) g_style[b * CIN + ci] = acc + sb[ci];
}

// ---------------------------------------------------------------------------
// Kernel 2: denom[b,co] = rsqrt( sum_ci style[b,ci]^2 * sum_k w[co,ci,k]^2 + eps )
// Block per co. Phase 1: v[ci] = sum_k w^2 (one sync). Phase 2: warp per 2 b.
// ---------------------------------------------------------------------------
__global__ void denom_kernel(const float* __restrict__ w) {
    int co = blockIdx.x;
    int ci = threadIdx.x;
    __shared__ float v[CIN];
    const float* wp = w + (size_t)co * (CIN * 9) + ci * 9;
    float s = 0.f;
#pragma unroll
    for (int k = 0; k < 9; k++) s = fmaf(wp[k], wp[k], s);
    v[ci] = s;
    __syncthreads();

    int warp = threadIdx.x >> 5;
    int lane = threadIdx.x & 31;
#pragma unroll
    for (int bb = 0; bb < 2; bb++) {
        int b = warp * 2 + bb;
        float acc = 0.f;
#pragma unroll
        for (int c = lane; c < CIN; c += 32) {
            float st = g_style[b * CIN + c];
            acc = fmaf(st * st, v[c], acc);
        }
#pragma unroll
        for (int off = 16; off > 0; off >>= 1)
            acc += __shfl_xor_sync(0xffffffffu, acc, off);
        if (lane == 0) g_denom[b * COUT + co] = rsqrtf(acc + EPSV);
    }
}

// ---------------------------------------------------------------------------
// Kernel 3: shared-weight conv, style folded into x, demod folded into output.
// Block: 128 cout x (2 rows x 64 cols) of one b. 256 threads: 8co x 8px each.
// Accumulators paired over oc (FFMA2); w pairs come straight from LDS.64.
// ---------------------------------------------------------------------------
__global__ __launch_bounds__(256, 2)
void conv_kernel(const float* __restrict__ x,
                 const float* __restrict__ w,
                 const float* __restrict__ bias,
                 float* __restrict__ out) {
    __shared__ __align__(16) float sW[CICHUNK * SW_CISTRIDE];
    __shared__ __align__(16) float sX[CICHUNK * SX_ROWS * SX_COLS];
    __shared__ float sStyle[CIN];

    const int b   = blockIdx.z;
    const int co0 = blockIdx.y * COTILE;
    const int r0  = blockIdx.x * 2;
    const int tid = threadIdx.x;

    for (int i = tid; i < CIN; i += 256) sStyle[i] = g_style[b * CIN + i];

    const int cog     = tid >> 4;          // 0..15
    const int pxg     = tid & 15;          // 0..15
    const int orow    = pxg >> 3;          // 0..1
    const int colbase = (pxg & 7) * 8;     // 0..56
    const int cobase  = cog * 8;           // 0..120

    // acc2[p][q]: p = pixel 0..7, q = oc-pair 0..3; .lo = oc 2q, .hi = oc 2q+1
    unsigned long long acc2[8][4];
#pragma unroll
    for (int p = 0; p < 8; p++)
#pragma unroll
        for (int q = 0; q < 4; q++) acc2[p][q] = 0ull;

    for (int chunk = 0; chunk < NCHUNK; chunk++) {
        const int ci0 = chunk * CICHUNK;
        __syncthreads();  // smem reuse (also orders sStyle fill on first iter)

        // --- load W chunk: [ci][tap][co] ---
#pragma unroll
        for (int it = 0; it < 4; it++) {
            int idx = tid + it * 256;      // 0..1023 = 128co x 8ci
            int co  = idx >> 3;
            int ci  = idx & 7;
            const float* gp = w + (size_t)(co0 + co) * (CIN * 9) + (ci0 + ci) * 9;
            float* sp = sW + ci * SW_CISTRIDE + co;
#pragma unroll
            for (int k = 0; k < 9; k++) sp[k * COTILE] = gp[k];
        }

        // --- load X halo tile, style-scaled, zero-padded ---
        for (int idx = tid; idx < CICHUNK * SX_ROWS * SX_COLS; idx += 256) {
            int ci  = idx / (SX_ROWS * SX_COLS);
            int rem = idx - ci * (SX_ROWS * SX_COLS);
            int rr  = rem / SX_COLS;
            int cc  = rem - rr * SX_COLS;
            int grow = r0 - 1 + rr;
            int gcol = cc - 1;
            float v = 0.f;
            if (grow >= 0 && grow < HGT && gcol >= 0 && gcol < WID && cc < 66) {
                v = x[(((size_t)(b * CIN + ci0 + ci)) * HGT + grow) * WID + gcol]
                    * sStyle[ci0 + ci];
            }
            sX[idx] = v;
        }
        __syncthreads();

        // --- compute: 8 ci x 3 ky x 3 kx x 8 px x 4 oc-pairs ---
#pragma unroll
        for (int ci = 0; ci < CICHUNK; ci++) {
            const float* xrow = sX + ci * (SX_ROWS * SX_COLS) + orow * SX_COLS + colbase;
            const float* wrow = sW + ci * SW_CISTRIDE + cobase;
#pragma unroll
            for (int ky = 0; ky < 3; ky++) {
                // vectorized x loads: 16B-aligned (all index terms mult of 4)
                float xv[10];
                const float* xr = xrow + ky * SX_COLS;
                {
                    float4 a = *(const float4*)(xr);
                    float4 c = *(const float4*)(xr + 4);
                    float2 e = *(const float2*)(xr + 8);
                    xv[0]=a.x; xv[1]=a.y; xv[2]=a.z; xv[3]=a.w;
                    xv[4]=c.x; xv[5]=c.y; xv[6]=c.z; xv[7]=c.w;
                    xv[8]=e.x; xv[9]=e.y;
                }
#pragma unroll
                for (int kx = 0; kx < 3; kx++) {
                    // w pairs: direct 64-bit LDS, no packing movs
                    const float* wp = wrow + (ky * 3 + kx) * COTILE;
                    unsigned long long wq[4];
#pragma unroll
                    for (int q = 0; q < 4; q++)
                        wq[q] = *(const unsigned long long*)(wp + 2 * q);
#pragma unroll
                    for (int p = 0; p < 8; p++) {
                        unsigned long long xb;
                        asm("mov.b64 %0, {%1, %1};" : "=l"(xb) : "f"(xv[kx + p]));
#pragma unroll
                        for (int q = 0; q < 4; q++) {
                            asm("fma.rn.f32x2 %0, %1, %2, %0;"
                                : "+l"(acc2[p][q]) : "l"(wq[q]), "l"(xb));
                        }
                    }
                }
            }
        }
    }

    // --- epilogue: demod scale + bias, vectorized stores ---
    const int gr = r0 + orow;
#pragma unroll
    for (int q = 0; q < 4; q++) {
        int oc0 = co0 + cobase + 2 * q;
        float d0 = g_denom[b * COUT + oc0];
        float d1 = g_denom[b * COUT + oc0 + 1];
        float b0 = bias[oc0];
        float b1 = bias[oc0 + 1];
        float r0v[8], r1v[8];
#pragma unroll
        for (int p = 0; p < 8; p++) {
            float lo, hi;
            asm("mov.b64 {%0, %1}, %2;" : "=f"(lo), "=f"(hi) : "l"(acc2[p][q]));
            r0v[p] = fmaf(lo, d0, b0);
            r1v[p] = fmaf(hi, d1, b1);
        }
        float4* op0 = (float4*)(out + (((size_t)(b * COUT + oc0)) * HGT + gr) * WID + colbase);
        float4* op1 = (float4*)(out + (((size_t)(b * COUT + oc0 + 1)) * HGT + gr) * WID + colbase);
        op0[0] = make_float4(r0v[0], r0v[1], r0v[2], r0v[3]);
        op0[1] = make_float4(r0v[4], r0v[5], r0v[6], r0v[7]);
        op1[0] = make_float4(r1v[0], r1v[1], r1v[2], r1v[3]);
        op1[1] = make_float4(r1v[4], r1v[5], r1v[6], r1v[7]);
    }
}

// ---------------------------------------------------------------------------
extern "C" void kernel_launch(void* const* d_in, const int* in_sizes, int n_in,
                              void* d_out, int out_size) {
    const float* x   = (const float*)d_in[0];  // [16,256,64,64]
    const float* y   = (const float*)d_in[1];  // [16,512]
    const float* w   = (const float*)d_in[2];  // [256,256,3,3]
    const float* bs  = (const float*)d_in[3];  // [256]
    const float* swt = (const float*)d_in[4];  // [256,512]
    const float* sbv = (const float*)d_in[5];  // [256]
    float* out = (float*)d_out;

    style_kernel<<<BATCH * CIN / 8, 256>>>(y, swt, sbv);
    denom_kernel<<<COUT, 256>>>(w);

    dim3 grid(HGT / 2, COUT / COTILE, BATCH);  // (32, 2, 16)
    conv_kernel<<<grid, 256>>>(x, w, bs, out);
}

// round 10
// speedup vs baseline: 1.3881x; 1.3862x over previous
#include <cuda_runtime.h>
#include <cuda_bf16.h>
#include <cstdint>

#define BATCH 16
#define CIN   256
#define COUT  256
#define HGT   64
#define WID   64
#define SDIM  512
#define EPSV  1e-8f
#define NTAP  9

#define CICH  32                     // ci per chunk
#define NCH   (CIN / CICH)           // 8
#define CELL  80                     // bytes per 32-ci bf16 cell (64B data + 16 pad)
#define XRR   6                      // halo rows (4 output rows + 2)
#define XCC   66                     // halo cols (-1..64)
#define XBYTES (XRR * XCC * CELL)    // 31680 per hi/lo
#define WBYTES (128 * CELL)          // 10240 per array
// smem: xh, xl, w[2 buf][h,l]
#define SMEM_BYTES (2 * XBYTES + 4 * WBYTES)   // 104320

__device__ float g_style[BATCH * CIN];
__device__ float g_denom[BATCH * COUT];
__device__ __nv_bfloat16 g_whb[NTAP * COUT * CIN];
__device__ __nv_bfloat16 g_wlb[NTAP * COUT * CIN];

// ---------------------------------------------------------------------------
__global__ void style_kernel(const float* __restrict__ y,
                             const float* __restrict__ sw,
                             const float* __restrict__ sb) {
    int widx = blockIdx.x * 8 + (threadIdx.x >> 5);
    int lane = threadIdx.x & 31;
    int b = widx >> 8, ci = widx & 255;
    const float* yr = y + b * SDIM;
    const float* wr = sw + (size_t)ci * SDIM;
    float acc = 0.f;
#pragma unroll
    for (int s = lane; s < SDIM; s += 32) acc = fmaf(yr[s], wr[s], acc);
#pragma unroll
    for (int off = 16; off > 0; off >>= 1) acc += __shfl_xor_sync(0xffffffffu, acc, off);
    if (lane == 0) g_style[b * CIN + ci] = acc + sb[ci];
}

__global__ void denom_kernel(const float* __restrict__ w) {
    int co = blockIdx.x, ci = threadIdx.x;
    __shared__ float v[CIN];
    const float* wp = w + (size_t)co * (CIN * 9) + ci * 9;
    float s = 0.f;
#pragma unroll
    for (int k = 0; k < 9; k++) s = fmaf(wp[k], wp[k], s);
    v[ci] = s;
    __syncthreads();
    int warp = threadIdx.x >> 5, lane = threadIdx.x & 31;
#pragma unroll
    for (int bb = 0; bb < 2; bb++) {
        int b = warp * 2 + bb;
        float acc = 0.f;
#pragma unroll
        for (int c = lane; c < CIN; c += 32) {
            float st = g_style[b * CIN + c];
            acc = fmaf(st * st, v[c], acc);
        }
#pragma unroll
        for (int off = 16; off > 0; off >>= 1) acc += __shfl_xor_sync(0xffffffffu, acc, off);
        if (lane == 0) g_denom[b * COUT + co] = rsqrtf(acc + EPSV);
    }
}

// w[co][ci][tap] -> bf16 hi/lo [tap][co][ci]
__global__ void wsplit_kernel(const float* __restrict__ w) {
    int s = blockIdx.x * 256 + threadIdx.x;
    if (s >= COUT * CIN * 9) return;
    int co = s / (CIN * 9);
    int rem = s - co * (CIN * 9);
    int ci = rem / 9;
    int tap = rem - ci * 9;
    float v = w[s];
    __nv_bfloat16 h = __float2bfloat16(v);
    __nv_bfloat16 l = __float2bfloat16(v - __bfloat162float(h));
    size_t d = ((size_t)tap * COUT + co) * CIN + ci;
    g_whb[d] = h;
    g_wlb[d] = l;
}

// ---------------------------------------------------------------------------
__device__ __forceinline__ void mma_bf16(float* c, uint32_t a0, uint32_t a1,
                                         uint32_t a2, uint32_t a3,
                                         uint32_t b0, uint32_t b1) {
    asm volatile(
        "mma.sync.aligned.m16n8k16.row.col.f32.bf16.bf16.f32 "
        "{%0,%1,%2,%3}, {%4,%5,%6,%7}, {%8,%9}, {%0,%1,%2,%3};"
        : "+f"(c[0]), "+f"(c[1]), "+f"(c[2]), "+f"(c[3])
        : "r"(a0), "r"(a1), "r"(a2), "r"(a3), "r"(b0), "r"(b1));
}

// ---------------------------------------------------------------------------
// conv_mma: implicit-GEMM conv, bf16 3-pass, warp tile 64px x 64co.
// CTA: 1 b x 128 co x 256 px (4 rows). 8 warps: m=wid&3 (row), n=wid>>2 (co half).
// ---------------------------------------------------------------------------
__global__ __launch_bounds__(256, 1)
void conv_mma(const float* __restrict__ x,
              const float* __restrict__ bias,
              float* __restrict__ out) {
    extern __shared__ char dsm[];
    char* xh = dsm;                       // [rr][cc] cells of 32 ci bf16, stride 80
    char* xl = dsm + XBYTES;
    char* wb = dsm + 2 * XBYTES;          // [buf2][h/l][128 co x 80B]

    const int b   = blockIdx.z;
    const int co0 = blockIdx.y * 128;
    const int r0  = blockIdx.x * 4;
    const int tid = threadIdx.x;
    const int wid = tid >> 5, lane = tid & 31;
    const int m = wid & 3;                // output row within CTA
    const int n = wid >> 2;               // co half (0/1)
    const int lg = lane >> 2;             // fragment row/col group 0..7
    const int lt = lane & 3;              // k-pair group

    float C[4][8][4];
#pragma unroll
    for (int mt = 0; mt < 4; mt++)
#pragma unroll
        for (int nt = 0; nt < 8; nt++)
#pragma unroll
            for (int r = 0; r < 4; r++) C[mt][nt][r] = 0.f;

    for (int chunk = 0; chunk < NCH; chunk++) {
        const int ci0 = chunk * CICH;
        __syncthreads();
        // ---- stage x halo as bf16 hi/lo (style folded) ----
        for (int idx = tid; idx < CICH * XRR * XCC; idx += 256) {
            int ci  = idx / (XRR * XCC);
            int rem = idx - ci * (XRR * XCC);
            int rr  = rem / XCC;
            int cc  = rem - rr * XCC;
            int grow = r0 - 1 + rr;
            int gcol = cc - 1;
            float v = 0.f;
            if (grow >= 0 && grow < HGT && gcol >= 0 && gcol < WID) {
                v = x[(((size_t)(b * CIN + ci0 + ci)) * HGT + grow) * WID + gcol]
                    * g_style[b * CIN + ci0 + ci];
            }
            __nv_bfloat16 h = __float2bfloat16(v);
            __nv_bfloat16 l = __float2bfloat16(v - __bfloat162float(h));
            int off = (rr * XCC + cc) * CELL + ci * 2;
            *(__nv_bfloat16*)(xh + off) = h;
            *(__nv_bfloat16*)(xl + off) = l;
        }

        for (int tap = 0; tap < NTAP; tap++) {
            const int dy = tap / 3, dx = tap - dy * 3;
            char* wbh = wb + (tap & 1) * 2 * WBYTES;
            char* wbl = wbh + WBYTES;
            // ---- stage w tile [128 co x 32 ci] hi/lo (2x uint4 per thread/arr) ----
            {
                int co = tid >> 1, half = tid & 1;
                size_t g = ((size_t)tap * COUT + co0 + co) * CIN + ci0 + half * 16;
                const uint4* sh = (const uint4*)(g_whb + g);
                const uint4* sl = (const uint4*)(g_wlb + g);
                uint4* dh = (uint4*)(wbh + co * CELL + half * 32);
                uint4* dl = (uint4*)(wbl + co * CELL + half * 32);
                dh[0] = sh[0]; dh[1] = sh[1];
                dl[0] = sl[0]; dl[1] = sl[1];
            }
            __syncthreads();

#pragma unroll
            for (int ks = 0; ks < 2; ks++) {
                // ---- A fragments: 4 m-tiles x (hi,lo) ----
                uint32_t Ah[4][4], Al[4][4];
#pragma unroll
                for (int mt = 0; mt < 4; mt++) {
                    int cell = (m + dy) * XCC + 16 * mt + lg + dx;
                    int o0 = cell * CELL + ks * 32 + lt * 4;
                    int o1 = o0 + 8 * CELL;          // rows +8
                    Ah[mt][0] = *(const uint32_t*)(xh + o0);
                    Ah[mt][1] = *(const uint32_t*)(xh + o1);
                    Ah[mt][2] = *(const uint32_t*)(xh + o0 + 16);
                    Ah[mt][3] = *(const uint32_t*)(xh + o1 + 16);
                    Al[mt][0] = *(const uint32_t*)(xl + o0);
                    Al[mt][1] = *(const uint32_t*)(xl + o1);
                    Al[mt][2] = *(const uint32_t*)(xl + o0 + 16);
                    Al[mt][3] = *(const uint32_t*)(xl + o1 + 16);
                }
#pragma unroll
                for (int nt = 0; nt < 8; nt++) {
                    int co_l = 64 * n + 8 * nt + lg;
                    int ob = co_l * CELL + ks * 32 + lt * 4;
                    uint32_t bh0 = *(const uint32_t*)(wbh + ob);
                    uint32_t bh1 = *(const uint32_t*)(wbh + ob + 16);
                    uint32_t bl0 = *(const uint32_t*)(wbl + ob);
                    uint32_t bl1 = *(const uint32_t*)(wbl + ob + 16);
#pragma unroll
                    for (int mt = 0; mt < 4; mt++) {
                        mma_bf16(C[mt][nt], Ah[mt][0], Ah[mt][1], Ah[mt][2], Ah[mt][3], bh0, bh1);
                        mma_bf16(C[mt][nt], Al[mt][0], Al[mt][1], Al[mt][2], Al[mt][3], bh0, bh1);
                        mma_bf16(C[mt][nt], Ah[mt][0], Ah[mt][1], Ah[mt][2], Ah[mt][3], bl0, bl1);
                    }
                }
            }
        }
    }

    // ---- epilogue: D * denom + bias ----
    const int orow = r0 + m;
#pragma unroll
    for (int nt = 0; nt < 8; nt++) {
        int co = co0 + 64 * n + 8 * nt + lt * 2;
        float d0 = g_denom[b * COUT + co];
        float d1 = g_denom[b * COUT + co + 1];
        float b0 = bias[co];
        float b1 = bias[co + 1];
        float* o0 = out + (((size_t)(b * COUT + co)) * HGT + orow) * WID;
        float* o1 = out + (((size_t)(b * COUT + co + 1)) * HGT + orow) * WID;
#pragma unroll
        for (int mt = 0; mt < 4; mt++) {
            int oc0 = 16 * mt + lg;
            o0[oc0]     = fmaf(C[mt][nt][0], d0, b0);
            o1[oc0]     = fmaf(C[mt][nt][1], d1, b1);
            o0[oc0 + 8] = fmaf(C[mt][nt][2], d0, b0);
            o1[oc0 + 8] = fmaf(C[mt][nt][3], d1, b1);
        }
    }
}

// ---------------------------------------------------------------------------
extern "C" void kernel_launch(void* const* d_in, const int* in_sizes, int n_in,
                              void* d_out, int out_size) {
    const float* x   = (const float*)d_in[0];
    const float* y   = (const float*)d_in[1];
    const float* w   = (const float*)d_in[2];
    const float* bs  = (const float*)d_in[3];
    const float* swt = (const float*)d_in[4];
    const float* sbv = (const float*)d_in[5];
    float* out = (float*)d_out;

    cudaFuncSetAttribute(conv_mma, cudaFuncAttributeMaxDynamicSharedMemorySize, SMEM_BYTES);

    style_kernel<<<BATCH * CIN / 8, 256>>>(y, swt, sbv);
    denom_kernel<<<COUT, 256>>>(w);
    wsplit_kernel<<<(COUT * CIN * 9 + 255) / 256, 256>>>(w);

    dim3 grid(HGT / 4, COUT / 128, BATCH);    // (16, 2, 16) = 512 CTAs
    conv_mma<<<grid, 256, SMEM_BYTES>>>(x, bs, out);
}

// round 12
// speedup vs baseline: 1.4052x; 1.0123x over previous
#include <cuda_runtime.h>
#include <cuda_bf16.h>
#include <cstdint>

#define BATCH 16
#define CIN   256
#define COUT  256
#define HGT   64
#define WID   64
#define SDIM  512
#define EPSV  1e-8f
#define NTAP  9

#define CICH  32                     // ci per chunk
#define NCH   (CIN / CICH)           // 8
#define CELL  80                     // bytes per 32-ci bf16 cell (64B data + 16 pad)
#define XRR   6                      // halo rows (4 output rows + 2)
#define XCC   66                     // halo cols (-1..64)
#define XBYTES (XRR * XCC * CELL)    // 31680 per hi/lo
#define WBYTES (128 * CELL)          // 10240 per array
#define SMEM_BYTES (2 * XBYTES + 4 * WBYTES)   // 104320

__device__ float g_style[BATCH * CIN];
__device__ float g_denom[BATCH * COUT];
__device__ __nv_bfloat16 g_whb[NTAP * COUT * CIN];
__device__ __nv_bfloat16 g_wlb[NTAP * COUT * CIN];

// ---------------------------------------------------------------------------
__global__ void style_kernel(const float* __restrict__ y,
                             const float* __restrict__ sw,
                             const float* __restrict__ sb) {
    int widx = blockIdx.x * 8 + (threadIdx.x >> 5);
    int lane = threadIdx.x & 31;
    int b = widx >> 8, ci = widx & 255;
    const float* yr = y + b * SDIM;
    const float* wr = sw + (size_t)ci * SDIM;
    float acc = 0.f;
#pragma unroll
    for (int s = lane; s < SDIM; s += 32) acc = fmaf(yr[s], wr[s], acc);
#pragma unroll
    for (int off = 16; off > 0; off >>= 1) acc += __shfl_xor_sync(0xffffffffu, acc, off);
    if (lane == 0) g_style[b * CIN + ci] = acc + sb[ci];
}

__global__ void denom_kernel(const float* __restrict__ w) {
    int co = blockIdx.x, ci = threadIdx.x;
    __shared__ float v[CIN];
    const float* wp = w + (size_t)co * (CIN * 9) + ci * 9;
    float s = 0.f;
#pragma unroll
    for (int k = 0; k < 9; k++) s = fmaf(wp[k], wp[k], s);
    v[ci] = s;
    __syncthreads();
    int warp = threadIdx.x >> 5, lane = threadIdx.x & 31;
#pragma unroll
    for (int bb = 0; bb < 2; bb++) {
        int b = warp * 2 + bb;
        float acc = 0.f;
#pragma unroll
        for (int c = lane; c < CIN; c += 32) {
            float st = g_style[b * CIN + c];
            acc = fmaf(st * st, v[c], acc);
        }
#pragma unroll
        for (int off = 16; off > 0; off >>= 1) acc += __shfl_xor_sync(0xffffffffu, acc, off);
        if (lane == 0) g_denom[b * COUT + co] = rsqrtf(acc + EPSV);
    }
}

// w[co][ci][tap] -> bf16 hi/lo [tap][co][ci]
__global__ void wsplit_kernel(const float* __restrict__ w) {
    int s = blockIdx.x * 256 + threadIdx.x;
    if (s >= COUT * CIN * 9) return;
    int co = s / (CIN * 9);
    int rem = s - co * (CIN * 9);
    int ci = rem / 9;
    int tap = rem - ci * 9;
    float v = w[s];
    __nv_bfloat16 h = __float2bfloat16(v);
    __nv_bfloat16 l = __float2bfloat16(v - __bfloat162float(h));
    size_t d = ((size_t)tap * COUT + co) * CIN + ci;
    g_whb[d] = h;
    g_wlb[d] = l;
}

// ---------------------------------------------------------------------------
__device__ __forceinline__ void mma_bf16(float* c, const uint32_t* a,
                                         uint32_t b0, uint32_t b1) {
    asm volatile(
        "mma.sync.aligned.m16n8k16.row.col.f32.bf16.bf16.f32 "
        "{%0,%1,%2,%3}, {%4,%5,%6,%7}, {%8,%9}, {%0,%1,%2,%3};"
        : "+f"(c[0]), "+f"(c[1]), "+f"(c[2]), "+f"(c[3])
        : "r"(a[0]), "r"(a[1]), "r"(a[2]), "r"(a[3]), "r"(b0), "r"(b1));
}

// ---------------------------------------------------------------------------
// conv_mma: implicit-GEMM conv, bf16 3-pass (pass-major: acc reuse distance 32).
// CTA: 1 b x 128 co x 256 px (4 rows). 8 warps: warp tile 64px x 64co.
// ---------------------------------------------------------------------------
__global__ __launch_bounds__(256, 1)
void conv_mma(const float* __restrict__ x,
              const float* __restrict__ bias,
              float* __restrict__ out) {
    extern __shared__ char dsm[];
    char* xh = dsm;                       // [rr][cc] cells of 32 ci bf16, stride 80
    char* xl = dsm + XBYTES;
    char* wb = dsm + 2 * XBYTES;          // [buf2][h/l][128 co x 80B]

    const int b   = blockIdx.z;
    const int co0 = blockIdx.y * 128;
    const int r0  = blockIdx.x * 4;
    const int tid = threadIdx.x;
    const int wid = tid >> 5, lane = tid & 31;
    const int m = wid & 3;                // output row within CTA
    const int n = wid >> 2;               // co half (0/1)
    const int lg = lane >> 2;             // fragment row/col group 0..7
    const int lt = lane & 3;              // k-pair group

    float C[4][8][4];
#pragma unroll
    for (int mt = 0; mt < 4; mt++)
#pragma unroll
        for (int nt = 0; nt < 8; nt++)
#pragma unroll
            for (int r = 0; r < 4; r++) C[mt][nt][r] = 0.f;

    for (int chunk = 0; chunk < NCH; chunk++) {
        const int ci0 = chunk * CICH;
        __syncthreads();
        // ---- stage x halo as bf16 hi/lo (style folded) ----
        for (int idx = tid; idx < CICH * XRR * XCC; idx += 256) {
            int ci  = idx / (XRR * XCC);
            int rem = idx - ci * (XRR * XCC);
            int rr  = rem / XCC;
            int cc  = rem - rr * XCC;
            int grow = r0 - 1 + rr;
            int gcol = cc - 1;
            float v = 0.f;
            if (grow >= 0 && grow < HGT && gcol >= 0 && gcol < WID) {
                v = x[(((size_t)(b * CIN + ci0 + ci)) * HGT + grow) * WID + gcol]
                    * g_style[b * CIN + ci0 + ci];
            }
            __nv_bfloat16 h = __float2bfloat16(v);
            __nv_bfloat16 l = __float2bfloat16(v - __bfloat162float(h));
            int off = (rr * XCC + cc) * CELL + ci * 2;
            *(__nv_bfloat16*)(xh + off) = h;
            *(__nv_bfloat16*)(xl + off) = l;
        }

        for (int tap = 0; tap < NTAP; tap++) {
            const int dy = tap / 3, dx = tap - dy * 3;
            char* wbh = wb + (tap & 1) * 2 * WBYTES;
            char* wbl = wbh + WBYTES;
            // ---- stage w tile [128 co x 32 ci] hi/lo ----
            {
                int co = tid >> 1, half = tid & 1;
                size_t g = ((size_t)tap * COUT + co0 + co) * CIN + ci0 + half * 16;
                const uint4* sh = (const uint4*)(g_whb + g);
                const uint4* sl = (const uint4*)(g_wlb + g);
                uint4* dh = (uint4*)(wbh + co * CELL + half * 32);
                uint4* dl = (uint4*)(wbl + co * CELL + half * 32);
                dh[0] = sh[0]; dh[1] = sh[1];
                dl[0] = sl[0]; dl[1] = sl[1];
            }
            __syncthreads();

#pragma unroll
            for (int ks = 0; ks < 2; ks++) {
                // ---- A fragments: 4 m-tiles x (hi,lo) ----
                uint32_t Ah[4][4], Al[4][4];
#pragma unroll
                for (int mt = 0; mt < 4; mt++) {
                    int cell = (m + dy) * XCC + 16 * mt + lg + dx;
                    int o0 = cell * CELL + ks * 32 + lt * 4;
                    int o1 = o0 + 8 * CELL;          // rows +8
                    Ah[mt][0] = *(const uint32_t*)(xh + o0);
                    Ah[mt][1] = *(const uint32_t*)(xh + o1);
                    Ah[mt][2] = *(const uint32_t*)(xh + o0 + 16);
                    Ah[mt][3] = *(const uint32_t*)(xh + o1 + 16);
                    Al[mt][0] = *(const uint32_t*)(xl + o0);
                    Al[mt][1] = *(const uint32_t*)(xl + o1);
                    Al[mt][2] = *(const uint32_t*)(xl + o0 + 16);
                    Al[mt][3] = *(const uint32_t*)(xl + o1 + 16);
                }
                // ---- pass 0: Ah x Bh (32 independent MMAs) ----
#pragma unroll
                for (int nt = 0; nt < 8; nt++) {
                    int ob = (64 * n + 8 * nt + lg) * CELL + ks * 32 + lt * 4;
                    uint32_t b0 = *(const uint32_t*)(wbh + ob);
                    uint32_t b1 = *(const uint32_t*)(wbh + ob + 16);
#pragma unroll
                    for (int mt = 0; mt < 4; mt++) mma_bf16(C[mt][nt], Ah[mt], b0, b1);
                }
                // ---- pass 1: Al x Bh ----
#pragma unroll
                for (int nt = 0; nt < 8; nt++) {
                    int ob = (64 * n + 8 * nt + lg) * CELL + ks * 32 + lt * 4;
                    uint32_t b0 = *(const uint32_t*)(wbh + ob);
                    uint32_t b1 = *(const uint32_t*)(wbh + ob + 16);
#pragma unroll
                    for (int mt = 0; mt < 4; mt++) mma_bf16(C[mt][nt], Al[mt], b0, b1);
                }
                // ---- pass 2: Ah x Bl ----
#pragma unroll
                for (int nt = 0; nt < 8; nt++) {
                    int ob = (64 * n + 8 * nt + lg) * CELL + ks * 32 + lt * 4;
                    uint32_t b0 = *(const uint32_t*)(wbl + ob);
                    uint32_t b1 = *(const uint32_t*)(wbl + ob + 16);
#pragma unroll
                    for (int mt = 0; mt < 4; mt++) mma_bf16(C[mt][nt], Ah[mt], b0, b1);
                }
            }
        }
    }

    // ---- epilogue: D * denom + bias ----
    const int orow = r0 + m;
#pragma unroll
    for (int nt = 0; nt < 8; nt++) {
        int co = co0 + 64 * n + 8 * nt + lt * 2;
        float d0 = g_denom[b * COUT + co];
        float d1 = g_denom[b * COUT + co + 1];
        float b0 = bias[co];
        float b1 = bias[co + 1];
        float* o0 = out + (((size_t)(b * COUT + co)) * HGT + orow) * WID;
        float* o1 = out + (((size_t)(b * COUT + co + 1)) * HGT + orow) * WID;
#pragma unroll
        for (int mt = 0; mt < 4; mt++) {
            int oc0 = 16 * mt + lg;
            o0[oc0]     = fmaf(C[mt][nt][0], d0, b0);
            o1[oc0]     = fmaf(C[mt][nt][1], d1, b1);
            o0[oc0 + 8] = fmaf(C[mt][nt][2], d0, b0);
            o1[oc0 + 8] = fmaf(C[mt][nt][3], d1, b1);
        }
    }
}

// ---------------------------------------------------------------------------
extern "C" void kernel_launch(void* const* d_in, const int* in_sizes, int n_in,
                              void* d_out, int out_size) {
    const float* x   = (const float*)d_in[0];
    const float* y   = (const float*)d_in[1];
    const float* w   = (const float*)d_in[2];
    const float* bs  = (const float*)d_in[3];
    const float* swt = (const float*)d_in[4];
    const float* sbv = (const float*)d_in[5];
    float* out = (float*)d_out;

    cudaFuncSetAttribute(conv_mma, cudaFuncAttributeMaxDynamicSharedMemorySize, SMEM_BYTES);

    style_kernel<<<BATCH * CIN / 8, 256>>>(y, swt, sbv);
    denom_kernel<<<COUT, 256>>>(w);
    wsplit_kernel<<<(COUT * CIN * 9 + 255) / 256, 256>>>(w);

    dim3 grid(HGT / 4, COUT / 128, BATCH);    // (16, 2, 16) = 512 CTAs
    conv_mma<<<grid, 256, SMEM_BYTES>>>(x, bs, out);
}

// round 13
// speedup vs baseline: 1.8966x; 1.3497x over previous
#include <cuda_runtime.h>
#include <cuda_bf16.h>
#include <cstdint>

#define BATCH 16
#define CIN   256
#define COUT  256
#define HGT   64
#define WID   64
#define SDIM  512
#define EPSV  1e-8f
#define NTAP  9

#define CICH  32                     // ci per chunk
#define NCH   (CIN / CICH)           // 8
#define CELL  80                     // bytes per 32-ci bf16 cell (64B + 16 pad)
#define XRR   6                      // halo rows
#define XCC   66                     // halo cols
#define XBYTES (XRR * XCC * CELL)    // 31680 per hi/lo
#define WBYTES (128 * CELL)          // 10240 per array
#define SMEM_BYTES (2 * XBYTES + 4 * WBYTES)   // 104320

__device__ float g_style[BATCH * CIN];
__device__ float g_denom[BATCH * COUT];
__device__ __nv_bfloat16 g_whb[NTAP * COUT * CIN];
__device__ __nv_bfloat16 g_wlb[NTAP * COUT * CIN];

// ---------------------------------------------------------------------------
__global__ void style_kernel(const float* __restrict__ y,
                             const float* __restrict__ sw,
                             const float* __restrict__ sb) {
    int widx = blockIdx.x * 8 + (threadIdx.x >> 5);
    int lane = threadIdx.x & 31;
    int b = widx >> 8, ci = widx & 255;
    const float* yr = y + b * SDIM;
    const float* wr = sw + (size_t)ci * SDIM;
    float acc = 0.f;
#pragma unroll
    for (int s = lane; s < SDIM; s += 32) acc = fmaf(yr[s], wr[s], acc);
#pragma unroll
    for (int off = 16; off > 0; off >>= 1) acc += __shfl_xor_sync(0xffffffffu, acc, off);
    if (lane == 0) g_style[b * CIN + ci] = acc + sb[ci];
}

__global__ void denom_kernel(const float* __restrict__ w) {
    int co = blockIdx.x, ci = threadIdx.x;
    __shared__ float v[CIN];
    const float* wp = w + (size_t)co * (CIN * 9) + ci * 9;
    float s = 0.f;
#pragma unroll
    for (int k = 0; k < 9; k++) s = fmaf(wp[k], wp[k], s);
    v[ci] = s;
    __syncthreads();
    int warp = threadIdx.x >> 5, lane = threadIdx.x & 31;
#pragma unroll
    for (int bb = 0; bb < 2; bb++) {
        int b = warp * 2 + bb;
        float acc = 0.f;
#pragma unroll
        for (int c = lane; c < CIN; c += 32) {
            float st = g_style[b * CIN + c];
            acc = fmaf(st * st, v[c], acc);
        }
#pragma unroll
        for (int off = 16; off > 0; off >>= 1) acc += __shfl_xor_sync(0xffffffffu, acc, off);
        if (lane == 0) g_denom[b * COUT + co] = rsqrtf(acc + EPSV);
    }
}

__global__ void wsplit_kernel(const float* __restrict__ w) {
    int s = blockIdx.x * 256 + threadIdx.x;
    if (s >= COUT * CIN * 9) return;
    int co = s / (CIN * 9);
    int rem = s - co * (CIN * 9);
    int ci = rem / 9;
    int tap = rem - ci * 9;
    float v = w[s];
    __nv_bfloat16 h = __float2bfloat16(v);
    __nv_bfloat16 l = __float2bfloat16(v - __bfloat162float(h));
    size_t d = ((size_t)tap * COUT + co) * CIN + ci;
    g_whb[d] = h;
    g_wlb[d] = l;
}

// ---------------------------------------------------------------------------
__device__ __forceinline__ uint32_t smem_u32(const void* p) {
    uint32_t a;
    asm("{ .reg .u64 t; cvta.to.shared.u64 t, %1; cvt.u32.u64 %0, t; }" : "=r"(a) : "l"(p));
    return a;
}
__device__ __forceinline__ void ldmx4(uint32_t* r, uint32_t addr) {
    asm volatile("ldmatrix.sync.aligned.m8n8.x4.shared.b16 {%0,%1,%2,%3}, [%4];"
                 : "=r"(r[0]), "=r"(r[1]), "=r"(r[2]), "=r"(r[3]) : "r"(addr));
}
__device__ __forceinline__ void mma_bf16(float* c, const uint32_t* a,
                                         uint32_t b0, uint32_t b1) {
    asm volatile(
        "mma.sync.aligned.m16n8k16.row.col.f32.bf16.bf16.f32 "
        "{%0,%1,%2,%3}, {%4,%5,%6,%7}, {%8,%9}, {%0,%1,%2,%3};"
        : "+f"(c[0]), "+f"(c[1]), "+f"(c[2]), "+f"(c[3])
        : "r"(a[0]), "r"(a[1]), "r"(a[2]), "r"(a[3]), "r"(b0), "r"(b1));
}

// ---------------------------------------------------------------------------
// conv_mma: implicit-GEMM conv, bf16 3-pass, ldmatrix fragments.
// CTA: 1 b x 128 co x 256 px (4 rows). 16 warps: warp tile 64px x 32co.
// ---------------------------------------------------------------------------
__global__ __launch_bounds__(512, 1)
void conv_mma(const float* __restrict__ x,
              const float* __restrict__ bias,
              float* __restrict__ out) {
    extern __shared__ char dsm[];
    char* xh = dsm;
    char* xl = dsm + XBYTES;
    char* wb = dsm + 2 * XBYTES;

    const int b   = blockIdx.z;
    const int co0 = blockIdx.y * 128;
    const int r0  = blockIdx.x * 4;
    const int tid = threadIdx.x;
    const int wid = tid >> 5, lane = tid & 31;
    const int m = wid & 3;                // output row 0..3
    const int n = wid >> 2;               // co group 0..3 (32 co each)
    const int lg = lane >> 2;
    const int lt = lane & 3;

    // ldmatrix per-lane row/offset components
    const int aRow = lane & 15;                             // A: fragment row
    const int aK   = (lane >> 4) * 16;                      // A: k-half byte off
    const int bRow = (lane & 7) + ((lane >> 4) << 3);       // B: co row within 16
    const int bK   = ((lane >> 3) & 1) * 16;                // B: k-half byte off

    const uint32_t xh_s = smem_u32(xh);
    const uint32_t xl_s = smem_u32(xl);
    const uint32_t wb_s = smem_u32(wb);

    float C[4][4][4];
#pragma unroll
    for (int mt = 0; mt < 4; mt++)
#pragma unroll
        for (int nt = 0; nt < 4; nt++)
#pragma unroll
            for (int r = 0; r < 4; r++) C[mt][nt][r] = 0.f;

    for (int chunk = 0; chunk < NCH; chunk++) {
        const int ci0 = chunk * CICH;
        __syncthreads();
        // ---- stage x halo as bf16 hi/lo (style folded) ----
        for (int idx = tid; idx < CICH * XRR * XCC; idx += 512) {
            int ci  = idx / (XRR * XCC);
            int rem = idx - ci * (XRR * XCC);
            int rr  = rem / XCC;
            int cc  = rem - rr * XCC;
            int grow = r0 - 1 + rr;
            int gcol = cc - 1;
            float v = 0.f;
            if (grow >= 0 && grow < HGT && gcol >= 0 && gcol < WID) {
                v = x[(((size_t)(b * CIN + ci0 + ci)) * HGT + grow) * WID + gcol]
                    * g_style[b * CIN + ci0 + ci];
            }
            __nv_bfloat16 h = __float2bfloat16(v);
            __nv_bfloat16 l = __float2bfloat16(v - __bfloat162float(h));
            int off = (rr * XCC + cc) * CELL + ci * 2;
            *(__nv_bfloat16*)(xh + off) = h;
            *(__nv_bfloat16*)(xl + off) = l;
        }

        for (int tap = 0; tap < NTAP; tap++) {
            const int dy = tap / 3, dx = tap - dy * 3;
            const int buf = (tap & 1) * 2 * WBYTES;
            char* wbh = wb + buf;
            char* wbl = wbh + WBYTES;
            // ---- stage w tile [128 co x 32 ci] hi/lo (1 uint4 each) ----
            {
                int co = tid >> 2, q = tid & 3;
                size_t g = ((size_t)tap * COUT + co0 + co) * CIN + ci0 + q * 8;
                *(uint4*)(wbh + co * CELL + q * 16) = *(const uint4*)(g_whb + g);
                *(uint4*)(wbl + co * CELL + q * 16) = *(const uint4*)(g_wlb + g);
            }
            __syncthreads();

            const uint32_t aBase = ((m + dy) * XCC + dx + aRow) * CELL + aK;
            const uint32_t bBase = wb_s + buf + (32 * n + bRow) * CELL + bK;

#pragma unroll
            for (int ks = 0; ks < 2; ks++) {
                const uint32_t ksOff = ks * 32;
                // ---- B fragments: Bh/Bl for 32 co (2 ldmatrix.x4 each) ----
                uint32_t Bh[2][4], Bl[2][4];
#pragma unroll
                for (int p = 0; p < 2; p++) {
                    ldmx4(Bh[p], bBase + p * (16 * CELL) + ksOff);
                    ldmx4(Bl[p], bBase + p * (16 * CELL) + ksOff + WBYTES);
                }
                // ---- A fragments: 4 m-tiles x (hi,lo) ----
                uint32_t Ah[4][4], Al[4][4];
#pragma unroll
                for (int mt = 0; mt < 4; mt++) {
                    uint32_t ao = aBase + mt * (16 * CELL) + ksOff;
                    ldmx4(Ah[mt], xh_s + ao);
                    ldmx4(Al[mt], xl_s + ao);
                }
                // ---- 48 MMAs: pass-major, B reused from regs ----
#pragma unroll
                for (int nt = 0; nt < 4; nt++) {
                    uint32_t b0 = Bh[nt >> 1][(nt & 1) * 2];
                    uint32_t b1 = Bh[nt >> 1][(nt & 1) * 2 + 1];
#pragma unroll
                    for (int mt = 0; mt < 4; mt++) mma_bf16(C[mt][nt], Ah[mt], b0, b1);
                }
#pragma unroll
                for (int nt = 0; nt < 4; nt++) {
                    uint32_t b0 = Bh[nt >> 1][(nt & 1) * 2];
                    uint32_t b1 = Bh[nt >> 1][(nt & 1) * 2 + 1];
#pragma unroll
                    for (int mt = 0; mt < 4; mt++) mma_bf16(C[mt][nt], Al[mt], b0, b1);
                }
#pragma unroll
                for (int nt = 0; nt < 4; nt++) {
                    uint32_t b0 = Bl[nt >> 1][(nt & 1) * 2];
                    uint32_t b1 = Bl[nt >> 1][(nt & 1) * 2 + 1];
#pragma unroll
                    for (int mt = 0; mt < 4; mt++) mma_bf16(C[mt][nt], Ah[mt], b0, b1);
                }
            }
        }
    }

    // ---- epilogue: D * denom + bias ----
    const int orow = r0 + m;
#pragma unroll
    for (int nt = 0; nt < 4; nt++) {
        int co = co0 + 32 * n + 8 * nt + lt * 2;
        float d0 = g_denom[b * COUT + co];
        float d1 = g_denom[b * COUT + co + 1];
        float b0 = bias[co];
        float b1 = bias[co + 1];
        float* o0 = out + (((size_t)(b * COUT + co)) * HGT + orow) * WID;
        float* o1 = out + (((size_t)(b * COUT + co + 1)) * HGT + orow) * WID;
#pragma unroll
        for (int mt = 0; mt < 4; mt++) {
            int oc0 = 16 * mt + lg;
            o0[oc0]     = fmaf(C[mt][nt][0], d0, b0);
            o1[oc0]     = fmaf(C[mt][nt][1], d1, b1);
            o0[oc0 + 8] = fmaf(C[mt][nt][2], d0, b0);
            o1[oc0 + 8] = fmaf(C[mt][nt][3], d1, b1);
        }
    }
}

// ---------------------------------------------------------------------------
extern "C" void kernel_launch(void* const* d_in, const int* in_sizes, int n_in,
                              void* d_out, int out_size) {
    const float* x   = (const float*)d_in[0];
    const float* y   = (const float*)d_in[1];
    const float* w   = (const float*)d_in[2];
    const float* bs  = (const float*)d_in[3];
    const float* swt = (const float*)d_in[4];
    const float* sbv = (const float*)d_in[5];
    float* out = (float*)d_out;

    cudaFuncSetAttribute(conv_mma, cudaFuncAttributeMaxDynamicSharedMemorySize, SMEM_BYTES);

    style_kernel<<<BATCH * CIN / 8, 256>>>(y, swt, sbv);
    denom_kernel<<<COUT, 256>>>(w);
    wsplit_kernel<<<(COUT * CIN * 9 + 255) / 256, 256>>>(w);

    dim3 grid(HGT / 4, COUT / 128, BATCH);    // (16, 2, 16) = 512 CTAs
    conv_mma<<<grid, 512, SMEM_BYTES>>>(x, bs, out);
}

// round 15
// speedup vs baseline: 2.2018x; 1.1609x over previous
#include <cuda_runtime.h>
#include <cuda_bf16.h>
#include <cstdint>

#define BATCH 16
#define CIN   256
#define COUT  256
#define HGT   64
#define WID   64
#define SDIM  512
#define EPSV  1e-8f
#define NTAP  9

#define CICH  32
#define NCH   (CIN / CICH)            // 8
#define CELL  80                      // A cell stride in smem (64B data + 16 pad)
#define XCC   66                      // padded halo cols
#define XROWS 6                       // rows staged per chunk
#define XBYTES (XROWS * XCC * CELL)   // 31680 per hi/lo
#define WROW  592                     // w row stride in smem (576B data + 16 pad)
#define WSZ   (128 * WROW)            // 75776 per hi/lo
#define SMEM_BYTES (2 * XBYTES + 2 * WSZ)   // 214912

__device__ float g_style[BATCH * CIN];
__device__ float g_denom[BATCH * COUT];
// x pre-split: [b][chunk][rr 66][cc 66][ci 32] bf16, halo zeros + style folded
__device__ __nv_bfloat16 g_xh[BATCH * NCH * XCC * XCC * CICH];
__device__ __nv_bfloat16 g_xl[BATCH * NCH * XCC * XCC * CICH];
// w pre-split: [co][chunk][tap][ci 32] bf16
__device__ __nv_bfloat16 g_whb[COUT * NCH * NTAP * CICH];
__device__ __nv_bfloat16 g_wlb[COUT * NCH * NTAP * CICH];

// ---------------------------------------------------------------------------
__global__ void style_kernel(const float* __restrict__ y,
                             const float* __restrict__ sw,
                             const float* __restrict__ sb) {
    int widx = blockIdx.x * 8 + (threadIdx.x >> 5);
    int lane = threadIdx.x & 31;
    int b = widx >> 8, ci = widx & 255;
    const float* yr = y + b * SDIM;
    const float* wr = sw + (size_t)ci * SDIM;
    float acc = 0.f;
#pragma unroll
    for (int s = lane; s < SDIM; s += 32) acc = fmaf(yr[s], wr[s], acc);
#pragma unroll
    for (int off = 16; off > 0; off >>= 1) acc += __shfl_xor_sync(0xffffffffu, acc, off);
    if (lane == 0) g_style[b * CIN + ci] = acc + sb[ci];
}

__global__ void denom_kernel(const float* __restrict__ w) {
    int co = blockIdx.x, ci = threadIdx.x;
    __shared__ float v[CIN];
    const float* wp = w + (size_t)co * (CIN * 9) + ci * 9;
    float s = 0.f;
#pragma unroll
    for (int k = 0; k < 9; k++) s = fmaf(wp[k], wp[k], s);
    v[ci] = s;
    __syncthreads();
    int warp = threadIdx.x >> 5, lane = threadIdx.x & 31;
#pragma unroll
    for (int bb = 0; bb < 2; bb++) {
        int b = warp * 2 + bb;
        float acc = 0.f;
#pragma unroll
        for (int c = lane; c < CIN; c += 32) {
            float st = g_style[b * CIN + c];
            acc = fmaf(st * st, v[c], acc);
        }
#pragma unroll
        for (int off = 16; off > 0; off >>= 1) acc += __shfl_xor_sync(0xffffffffu, acc, off);
        if (lane == 0) g_denom[b * COUT + co] = rsqrtf(acc + EPSV);
    }
}

// w[co][ci][tap] -> bf16 hi/lo [co][chunk][tap][ci32]
__global__ void wsplit_kernel(const float* __restrict__ w) {
    int s = blockIdx.x * 256 + threadIdx.x;
    if (s >= COUT * CIN * 9) return;
    int co = s / (CIN * 9);
    int rem = s - co * (CIN * 9);
    int ci = rem / 9;
    int tap = rem - ci * 9;
    float v = w[s];
    __nv_bfloat16 h = __float2bfloat16(v);
    __nv_bfloat16 l = __float2bfloat16(v - __bfloat162float(h));
    size_t d = (((size_t)co * NCH + (ci >> 5)) * NTAP + tap) * CICH + (ci & 31);
    g_whb[d] = h;
    g_wlb[d] = l;
}

// x[b][ci][h][w] * style -> bf16 hi/lo padded [b][chunk][rr][cc][ci32]
__global__ void xsplit_kernel(const float* __restrict__ x) {
    int rr = blockIdx.x, chunk = blockIdx.y, b = blockIdx.z;
    int grow = rr - 1;
    __shared__ __nv_bfloat16 th[XCC * CICH], tl[XCC * CICH];
    int tid = threadIdx.x;
    for (int idx = tid; idx < CICH * XCC; idx += 512) {
        int ci = idx / XCC, cc = idx - ci * XCC;
        int gcol = cc - 1;
        float v = 0.f;
        if (grow >= 0 && grow < HGT && gcol >= 0 && gcol < WID)
            v = x[((size_t)(b * CIN + chunk * CICH + ci) * HGT + grow) * WID + gcol]
                * g_style[b * CIN + chunk * CICH + ci];
        __nv_bfloat16 h = __float2bfloat16(v);
        __nv_bfloat16 l = __float2bfloat16(v - __bfloat162float(h));
        th[cc * CICH + ci] = h;
        tl[cc * CICH + ci] = l;
    }
    __syncthreads();
    size_t obase = ((size_t)(b * NCH + chunk) * XCC + rr) * (XCC * CICH);
    const uint4* sh = (const uint4*)th;
    const uint4* sl = (const uint4*)tl;
    uint4* dh = (uint4*)(g_xh + obase);
    uint4* dl = (uint4*)(g_xl + obase);
    for (int i = tid; i < XCC * CICH / 8; i += 512) { dh[i] = sh[i]; dl[i] = sl[i]; }
}

// ---------------------------------------------------------------------------
__device__ __forceinline__ uint32_t smem_u32(const void* p) {
    uint32_t a;
    asm("{ .reg .u64 t; cvta.to.shared.u64 t, %1; cvt.u32.u64 %0, t; }" : "=r"(a) : "l"(p));
    return a;
}
__device__ __forceinline__ void cp16(uint32_t dst, const void* src) {
    asm volatile("cp.async.cg.shared.global [%0], [%1], 16;" :: "r"(dst), "l"(src));
}
__device__ __forceinline__ void ldmx4(uint32_t* r, uint32_t addr) {
    asm volatile("ldmatrix.sync.aligned.m8n8.x4.shared.b16 {%0,%1,%2,%3}, [%4];"
                 : "=r"(r[0]), "=r"(r[1]), "=r"(r[2]), "=r"(r[3]) : "r"(addr));
}
__device__ __forceinline__ void mma_bf16(float* c, const uint32_t* a,
                                         uint32_t b0, uint32_t b1) {
    asm volatile(
        "mma.sync.aligned.m16n8k16.row.col.f32.bf16.bf16.f32 "
        "{%0,%1,%2,%3}, {%4,%5,%6,%7}, {%8,%9}, {%0,%1,%2,%3};"
        : "+f"(c[0]), "+f"(c[1]), "+f"(c[2]), "+f"(c[3])
        : "r"(a[0]), "r"(a[1]), "r"(a[2]), "r"(a[3]), "r"(b0), "r"(b1));
}

// ---------------------------------------------------------------------------
// conv_mma: implicit-GEMM conv, bf16 3-pass, all staging via cp.async.
// CTA: 1 b x 128 co x 256 px (4 rows). 16 warps: warp tile 64px x 32co.
// Per chunk: one cp.async stage (x rows + w all 9 taps), 2 syncs, 864 HMMAs/warp.
// ---------------------------------------------------------------------------
__global__ __launch_bounds__(512, 1)
void conv_mma(const float* __restrict__ bias, float* __restrict__ out) {
    extern __shared__ char dsm[];
    const uint32_t xh_s = smem_u32(dsm);
    const uint32_t xl_s = xh_s + XBYTES;
    const uint32_t wb_s = xh_s + 2 * XBYTES;   // [h 128x592][l 128x592]

    const int b   = blockIdx.z;
    const int co0 = blockIdx.y * 128;
    const int r0  = blockIdx.x * 4;
    const int tid = threadIdx.x;
    const int wid = tid >> 5, lane = tid & 31;
    const int m = wid & 3;                // output row 0..3
    const int n = wid >> 2;               // co group 0..3
    const int lg = lane >> 2;
    const int lt = lane & 3;

    const int aRow = lane & 15;
    const int aK   = (lane >> 4) * 16;
    const int bRow = (lane & 7) + ((lane >> 4) << 3);
    const int bK   = ((lane >> 3) & 1) * 16;

    float C[4][4][4];
#pragma unroll
    for (int mt = 0; mt < 4; mt++)
#pragma unroll
        for (int nt = 0; nt < 4; nt++)
#pragma unroll
            for (int r = 0; r < 4; r++) C[mt][nt][r] = 0.f;

    for (int chunk = 0; chunk < NCH; chunk++) {
        __syncthreads();   // previous chunk's compute done; smem reusable

        // ---- stage x: 6 rows x 66 cells, hi+lo, cp.async 16B ----
        const size_t xgbase = ((size_t)(b * NCH + chunk) * XCC + r0) * (XCC * CICH);
        for (int i = tid; i < XROWS * XCC * 4; i += 512) {
            int j = i & 3, cell = i >> 2;
            uint32_t dst = xh_s + cell * CELL + j * 16;
            const __nv_bfloat16* srch = g_xh + xgbase + cell * CICH + j * 8;
            const __nv_bfloat16* srcl = g_xl + xgbase + cell * CICH + j * 8;
            cp16(dst, srch);
            cp16(dst + XBYTES, srcl);
        }
        // ---- stage w: 128 co x (9 taps x 32 ci = 576B), hi+lo ----
        for (int i = tid; i < 128 * 36; i += 512) {
            int co = i / 36, k = i - co * 36;
            size_t gw = ((size_t)(co0 + co) * NCH + chunk) * (NTAP * CICH) + k * 8;
            uint32_t dst = wb_s + co * WROW + k * 16;
            cp16(dst, g_whb + gw);
            cp16(dst + WSZ, g_wlb + gw);
        }
        asm volatile("cp.async.commit_group;" ::: "memory");
        asm volatile("cp.async.wait_group 0;" ::: "memory");
        __syncthreads();

        // ---- compute: 9 taps x 2 ks, no barriers ----
        for (int tap = 0; tap < NTAP; tap++) {
            const int dy = tap / 3, dx = tap - dy * 3;
            const uint32_t aBase = ((m + dy) * XCC + dx + aRow) * CELL + aK;
            const uint32_t bBase = wb_s + (32 * n + bRow) * WROW + tap * 64 + bK;

#pragma unroll
            for (int ks = 0; ks < 2; ks++) {
                const uint32_t ksOff = ks * 32;
                uint32_t Bh[2][4], Bl[2][4];
#pragma unroll
                for (int p = 0; p < 2; p++) {
                    ldmx4(Bh[p], bBase + p * (16 * WROW) + ksOff);
                    ldmx4(Bl[p], bBase + p * (16 * WROW) + ksOff + WSZ);
                }
                uint32_t Ah[4][4], Al[4][4];
#pragma unroll
                for (int mt = 0; mt < 4; mt++) {
                    uint32_t ao = aBase + mt * (16 * CELL) + ksOff;
                    ldmx4(Ah[mt], xh_s + ao);
                    ldmx4(Al[mt], xl_s + ao - XBYTES + XBYTES);  // xl region
                    Al[mt][0] = Al[mt][0];  // (no-op; clarity)
                }
                // correct xl loads (separate region)
#pragma unroll
                for (int mt = 0; mt < 4; mt++) {
                    uint32_t ao = aBase + mt * (16 * CELL) + ksOff;
                    ldmx4(Al[mt], xl_s + ao);
                }
#pragma unroll
                for (int nt = 0; nt < 4; nt++) {
                    uint32_t b0 = Bh[nt >> 1][(nt & 1) * 2];
                    uint32_t b1 = Bh[nt >> 1][(nt & 1) * 2 + 1];
#pragma unroll
                    for (int mt = 0; mt < 4; mt++) mma_bf16(C[mt][nt], Ah[mt], b0, b1);
                }
#pragma unroll
                for (int nt = 0; nt < 4; nt++) {
                    uint32_t b0 = Bh[nt >> 1][(nt & 1) * 2];
                    uint32_t b1 = Bh[nt >> 1][(nt & 1) * 2 + 1];
#pragma unroll
                    for (int mt = 0; mt < 4; mt++) mma_bf16(C[mt][nt], Al[mt], b0, b1);
                }
#pragma unroll
                for (int nt = 0; nt < 4; nt++) {
                    uint32_t b0 = Bl[nt >> 1][(nt & 1) * 2];
                    uint32_t b1 = Bl[nt >> 1][(nt & 1) * 2 + 1];
#pragma unroll
                    for (int mt = 0; mt < 4; mt++) mma_bf16(C[mt][nt], Ah[mt], b0, b1);
                }
            }
        }
    }

    // ---- epilogue: D * denom + bias ----
    const int orow = r0 + m;
#pragma unroll
    for (int nt = 0; nt < 4; nt++) {
        int co = co0 + 32 * n + 8 * nt + lt * 2;
        float d0 = g_denom[b * COUT + co];
        float d1 = g_denom[b * COUT + co + 1];
        float b0 = bias[co];
        float b1 = bias[co + 1];
        float* o0 = out + (((size_t)(b * COUT + co)) * HGT + orow) * WID;
        float* o1 = out + (((size_t)(b * COUT + co + 1)) * HGT + orow) * WID;
#pragma unroll
        for (int mt = 0; mt < 4; mt++) {
            int oc0 = 16 * mt + lg;
            o0[oc0]     = fmaf(C[mt][nt][0], d0, b0);
            o1[oc0]     = fmaf(C[mt][nt][1], d1, b1);
            o0[oc0 + 8] = fmaf(C[mt][nt][2], d0, b0);
            o1[oc0 + 8] = fmaf(C[mt][nt][3], d1, b1);
        }
    }
}

// ---------------------------------------------------------------------------
extern "C" void kernel_launch(void* const* d_in, const int* in_sizes, int n_in,
                              void* d_out, int out_size) {
    const float* x   = (const float*)d_in[0];
    const float* y   = (const float*)d_in[1];
    const float* w   = (const float*)d_in[2];
    const float* bs  = (const float*)d_in[3];
    const float* swt = (const float*)d_in[4];
    const float* sbv = (const float*)d_in[5];
    float* out = (float*)d_out;

    cudaFuncSetAttribute(conv_mma, cudaFuncAttributeMaxDynamicSharedMemorySize, SMEM_BYTES);

    style_kernel<<<BATCH * CIN / 8, 256>>>(y, swt, sbv);
    denom_kernel<<<COUT, 256>>>(w);
    wsplit_kernel<<<(COUT * CIN * 9 + 255) / 256, 256>>>(w);
    dim3 xg(XCC, NCH, BATCH);
    xsplit_kernel<<<xg, 512>>>(x);

    dim3 grid(HGT / 4, COUT / 128, BATCH);    // (16, 2, 16) = 512 CTAs
    conv_mma<<<grid, 512, SMEM_BYTES>>>(bs, out);
}

// round 16
// speedup vs baseline: 3.1883x; 1.4481x over previous
#include <cuda_runtime.h>
#include <cuda_fp16.h>
#include <cstdint>

#define BATCH 16
#define CIN   256
#define COUT  256
#define HGT   64
#define WID   64
#define SDIM  512
#define EPSV  1e-8f
#define NTAP  9

#define CICH  32
#define NCH   (CIN / CICH)            // 8
#define CELL  80                      // A cell stride in smem (64B data + 16 pad)
#define XCC   66                      // padded halo cols
#define XROWS 6                       // rows staged per chunk
#define XBYTES (XROWS * XCC * CELL)   // 31680 per hi/lo
#define WROW  592                     // w row stride in smem (576B data + 16 pad)
#define WSZ   (128 * WROW)            // 75776
#define SMEM_BYTES (2 * XBYTES + WSZ) // 139136

__device__ float g_style[BATCH * CIN];
__device__ float g_denom[BATCH * COUT];
// x pre-split: [b][chunk][rr 66][cc 66][ci 32] fp16 hi/lo, halo zeros + style folded
__device__ __half g_xh[BATCH * NCH * XCC * XCC * CICH];
__device__ __half g_xl[BATCH * NCH * XCC * XCC * CICH];
// w fp16: [co][chunk][tap][ci 32]
__device__ __half g_whb[COUT * NCH * NTAP * CICH];

// ---------------------------------------------------------------------------
__global__ void style_kernel(const float* __restrict__ y,
                             const float* __restrict__ sw,
                             const float* __restrict__ sb) {
    int widx = blockIdx.x * 8 + (threadIdx.x >> 5);
    int lane = threadIdx.x & 31;
    int b = widx >> 8, ci = widx & 255;
    const float* yr = y + b * SDIM;
    const float* wr = sw + (size_t)ci * SDIM;
    float acc = 0.f;
#pragma unroll
    for (int s = lane; s < SDIM; s += 32) acc = fmaf(yr[s], wr[s], acc);
#pragma unroll
    for (int off = 16; off > 0; off >>= 1) acc += __shfl_xor_sync(0xffffffffu, acc, off);
    if (lane == 0) g_style[b * CIN + ci] = acc + sb[ci];
}

__global__ void denom_kernel(const float* __restrict__ w) {
    int co = blockIdx.x, ci = threadIdx.x;
    __shared__ float v[CIN];
    const float* wp = w + (size_t)co * (CIN * 9) + ci * 9;
    float s = 0.f;
#pragma unroll
    for (int k = 0; k < 9; k++) s = fmaf(wp[k], wp[k], s);
    v[ci] = s;
    __syncthreads();
    int warp = threadIdx.x >> 5, lane = threadIdx.x & 31;
#pragma unroll
    for (int bb = 0; bb < 2; bb++) {
        int b = warp * 2 + bb;
        float acc = 0.f;
#pragma unroll
        for (int c = lane; c < CIN; c += 32) {
            float st = g_style[b * CIN + c];
            acc = fmaf(st * st, v[c], acc);
        }
#pragma unroll
        for (int off = 16; off > 0; off >>= 1) acc += __shfl_xor_sync(0xffffffffu, acc, off);
        if (lane == 0) g_denom[b * COUT + co] = rsqrtf(acc + EPSV);
    }
}

// w[co][ci][tap] -> fp16 [co][chunk][tap][ci32]
__global__ void wsplit_kernel(const float* __restrict__ w) {
    int s = blockIdx.x * 256 + threadIdx.x;
    if (s >= COUT * CIN * 9) return;
    int co = s / (CIN * 9);
    int rem = s - co * (CIN * 9);
    int ci = rem / 9;
    int tap = rem - ci * 9;
    size_t d = (((size_t)co * NCH + (ci >> 5)) * NTAP + tap) * CICH + (ci & 31);
    g_whb[d] = __float2half(w[s]);
}

// x[b][ci][h][w] * style -> fp16 hi/lo padded [b][chunk][rr][cc][ci32]
// smem tile stride 34 halfs (17 words): conflict-free transpose.
__global__ void xsplit_kernel(const float* __restrict__ x) {
    int rr = blockIdx.x, chunk = blockIdx.y, b = blockIdx.z;
    int grow = rr - 1;
    __shared__ __half th[XCC * 34], tl[XCC * 34];
    int tid = threadIdx.x;
    for (int idx = tid; idx < CICH * XCC; idx += 512) {
        int ci = idx / XCC, cc = idx - ci * XCC;
        int gcol = cc - 1;
        float v = 0.f;
        if (grow >= 0 && grow < HGT && gcol >= 0 && gcol < WID)
            v = x[((size_t)(b * CIN + chunk * CICH + ci) * HGT + grow) * WID + gcol]
                * g_style[b * CIN + chunk * CICH + ci];
        __half h = __float2half(v);
        __half l = __float2half(v - __half2float(h));
        th[cc * 34 + ci] = h;
        tl[cc * 34 + ci] = l;
    }
    __syncthreads();
    size_t obase = ((size_t)(b * NCH + chunk) * XCC + rr) * (XCC * CICH);
    uint32_t* dh = (uint32_t*)(g_xh + obase);
    uint32_t* dl = (uint32_t*)(g_xl + obase);
    for (int i = tid; i < XCC * 16; i += 512) {
        int cc = i >> 4, j = i & 15;
        dh[cc * 16 + j] = *(const uint32_t*)(th + cc * 34 + j * 2);
        dl[cc * 16 + j] = *(const uint32_t*)(tl + cc * 34 + j * 2);
    }
}

// ---------------------------------------------------------------------------
__device__ __forceinline__ uint32_t smem_u32(const void* p) {
    uint32_t a;
    asm("{ .reg .u64 t; cvta.to.shared.u64 t, %1; cvt.u32.u64 %0, t; }" : "=r"(a) : "l"(p));
    return a;
}
__device__ __forceinline__ void cp16(uint32_t dst, const void* src) {
    asm volatile("cp.async.cg.shared.global [%0], [%1], 16;" :: "r"(dst), "l"(src));
}
__device__ __forceinline__ void ldmx4(uint32_t* r, uint32_t addr) {
    asm volatile("ldmatrix.sync.aligned.m8n8.x4.shared.b16 {%0,%1,%2,%3}, [%4];"
                 : "=r"(r[0]), "=r"(r[1]), "=r"(r[2]), "=r"(r[3]) : "r"(addr));
}
__device__ __forceinline__ void mma_f16(float* c, const uint32_t* a,
                                        uint32_t b0, uint32_t b1) {
    asm volatile(
        "mma.sync.aligned.m16n8k16.row.col.f32.f16.f16.f32 "
        "{%0,%1,%2,%3}, {%4,%5,%6,%7}, {%8,%9}, {%0,%1,%2,%3};"
        : "+f"(c[0]), "+f"(c[1]), "+f"(c[2]), "+f"(c[3])
        : "r"(a[0]), "r"(a[1]), "r"(a[2]), "r"(a[3]), "r"(b0), "r"(b1));
}

// ---------------------------------------------------------------------------
// conv_mma: implicit-GEMM conv, fp16 2-pass (x = hi+lo, w = single fp16).
// CTA: 1 b x 128 co x 256 px (4 rows). 16 warps: warp tile 64px x 32co.
// Per chunk: one cp.async stage, 2 syncs, 576 HMMAs/warp over 9 taps.
// ---------------------------------------------------------------------------
__global__ __launch_bounds__(512, 1)
void conv_mma(const float* __restrict__ bias, float* __restrict__ out) {
    extern __shared__ char dsm[];
    const uint32_t xh_s = smem_u32(dsm);
    const uint32_t xl_s = xh_s + XBYTES;
    const uint32_t wb_s = xh_s + 2 * XBYTES;

    const int b   = blockIdx.z;
    const int co0 = blockIdx.y * 128;
    const int r0  = blockIdx.x * 4;
    const int tid = threadIdx.x;
    const int wid = tid >> 5, lane = tid & 31;
    const int m = wid & 3;
    const int n = wid >> 2;
    const int lg = lane >> 2;
    const int lt = lane & 3;

    const int aRow = lane & 15;
    const int aK   = (lane >> 4) * 16;
    const int bRow = (lane & 7) + ((lane >> 4) << 3);
    const int bK   = ((lane >> 3) & 1) * 16;

    float C[4][4][4];
#pragma unroll
    for (int mt = 0; mt < 4; mt++)
#pragma unroll
        for (int nt = 0; nt < 4; nt++)
#pragma unroll
            for (int r = 0; r < 4; r++) C[mt][nt][r] = 0.f;

    for (int chunk = 0; chunk < NCH; chunk++) {
        __syncthreads();

        // ---- stage x: 6 rows x 66 cells, hi+lo ----
        const size_t xgbase = ((size_t)(b * NCH + chunk) * XCC + r0) * (XCC * CICH);
        for (int i = tid; i < XROWS * XCC * 4; i += 512) {
            int j = i & 3, cell = i >> 2;
            uint32_t dst = xh_s + cell * CELL + j * 16;
            cp16(dst, g_xh + xgbase + cell * CICH + j * 8);
            cp16(dst + XBYTES, g_xl + xgbase + cell * CICH + j * 8);
        }
        // ---- stage w: 128 co x (9 taps x 32 ci = 576B) ----
        for (int i = tid; i < 128 * 36; i += 512) {
            int co = i / 36, k = i - co * 36;
            size_t gw = ((size_t)(co0 + co) * NCH + chunk) * (NTAP * CICH) + k * 8;
            cp16(wb_s + co * WROW + k * 16, g_whb + gw);
        }
        asm volatile("cp.async.commit_group;" ::: "memory");
        asm volatile("cp.async.wait_group 0;" ::: "memory");
        __syncthreads();

        // ---- compute: 9 taps x 2 ks, no barriers ----
        for (int tap = 0; tap < NTAP; tap++) {
            const int dy = tap / 3, dx = tap - dy * 3;
            const uint32_t aBase = ((m + dy) * XCC + dx + aRow) * CELL + aK;
            const uint32_t bBase = wb_s + (32 * n + bRow) * WROW + tap * 64 + bK;

#pragma unroll
            for (int ks = 0; ks < 2; ks++) {
                const uint32_t ksOff = ks * 32;
                uint32_t Bh[2][4];
#pragma unroll
                for (int p = 0; p < 2; p++)
                    ldmx4(Bh[p], bBase + p * (16 * WROW) + ksOff);
                uint32_t Ah[4][4], Al[4][4];
#pragma unroll
                for (int mt = 0; mt < 4; mt++) {
                    uint32_t ao = aBase + mt * (16 * CELL) + ksOff;
                    ldmx4(Ah[mt], xh_s + ao);
                    ldmx4(Al[mt], xl_s + ao);
                }
                // pass 0: Ah x Bh
#pragma unroll
                for (int nt = 0; nt < 4; nt++) {
                    uint32_t b0 = Bh[nt >> 1][(nt & 1) * 2];
                    uint32_t b1 = Bh[nt >> 1][(nt & 1) * 2 + 1];
#pragma unroll
                    for (int mt = 0; mt < 4; mt++) mma_f16(C[mt][nt], Ah[mt], b0, b1);
                }
                // pass 1: Al x Bh
#pragma unroll
                for (int nt = 0; nt < 4; nt++) {
                    uint32_t b0 = Bh[nt >> 1][(nt & 1) * 2];
                    uint32_t b1 = Bh[nt >> 1][(nt & 1) * 2 + 1];
#pragma unroll
                    for (int mt = 0; mt < 4; mt++) mma_f16(C[mt][nt], Al[mt], b0, b1);
                }
            }
        }
    }

    // ---- epilogue: D * denom + bias ----
    const int orow = r0 + m;
#pragma unroll
    for (int nt = 0; nt < 4; nt++) {
        int co = co0 + 32 * n + 8 * nt + lt * 2;
        float d0 = g_denom[b * COUT + co];
        float d1 = g_denom[b * COUT + co + 1];
        float b0 = bias[co];
        float b1 = bias[co + 1];
        float* o0 = out + (((size_t)(b * COUT + co)) * HGT + orow) * WID;
        float* o1 = out + (((size_t)(b * COUT + co + 1)) * HGT + orow) * WID;
#pragma unroll
        for (int mt = 0; mt < 4; mt++) {
            int oc0 = 16 * mt + lg;
            o0[oc0]     = fmaf(C[mt][nt][0], d0, b0);
            o1[oc0]     = fmaf(C[mt][nt][1], d1, b1);
            o0[oc0 + 8] = fmaf(C[mt][nt][2], d0, b0);
            o1[oc0 + 8] = fmaf(C[mt][nt][3], d1, b1);
        }
    }
}

// ---------------------------------------------------------------------------
extern "C" void kernel_launch(void* const* d_in, const int* in_sizes, int n_in,
                              void* d_out, int out_size) {
    const float* x   = (const float*)d_in[0];
    const float* y   = (const float*)d_in[1];
    const float* w   = (const float*)d_in[2];
    const float* bs  = (const float*)d_in[3];
    const float* swt = (const float*)d_in[4];
    const float* sbv = (const float*)d_in[5];
    float* out = (float*)d_out;

    cudaFuncSetAttribute(conv_mma, cudaFuncAttributeMaxDynamicSharedMemorySize, SMEM_BYTES);

    style_kernel<<<BATCH * CIN / 8, 256>>>(y, swt, sbv);
    denom_kernel<<<COUT, 256>>>(w);
    wsplit_kernel<<<(COUT * CIN * 9 + 255) / 256, 256>>>(w);
    dim3 xg(XCC, NCH, BATCH);
    xsplit_kernel<<<xg, 512>>>(x);

    dim3 grid(HGT / 4, COUT / 128, BATCH);    // (16, 2, 16) = 512 CTAs
    conv_mma<<<grid, 512, SMEM_BYTES>>>(bs, out);
}